// round 13
// baseline (speedup 1.0000x reference)
#include <cuda_runtime.h>
#include <math.h>
#include <stdint.h>

// B=8, n=32, C=64, O=64
// out: concat(o0[8,64], o1[8,32,64], o2[8,32,32,64], o3[8,32,32,32,64]) f32

#define O1_OFF 512
#define O2_OFF 16896
#define O3_OFF 541184

// ---------------- device scratch ----------------
__device__ __align__(16) float g_We3T[384 * 64];
__device__ __align__(16) float g_Wt3[8 * 12 * 2048];   // [b][chunk][frag-order], tf32
__device__ __align__(16) float g_Wt2[8 * 16 * 2048];   // [b][chunk][frag-order], tf32
__device__ __align__(16) float g_bias3[8 * 64];
__device__ __align__(16) float g_bias2[8 * 64];
__device__ __align__(16) float g_scal[8 * 10];
__device__ int g_flags[4];
__device__ __align__(16) float g_r3[8 * 32 * 32 * 128];
__device__ __align__(16) float g_y2[8 * 32 * 32 * 384];
__device__ __align__(16) float g_P1[8 * 32 * 32 * 64];
__device__ __align__(16) float g_P2[8 * 32 * 32 * 64];
__device__ __align__(16) float g_P3[8 * 32 * 32 * 64];

__device__ __forceinline__ float sigf(float x) { return 1.0f / (1.0f + __expf(-x)); }

__device__ __forceinline__ float to_tf32(float x) {
    uint32_t u;
    asm("cvt.rna.tf32.f32 %0, %1;" : "=r"(u) : "f"(x));
    return __uint_as_float(u);
}

__device__ __forceinline__ uint32_t smem_u32(const void* p) {
    uint32_t a;
    asm("{ .reg .u64 t; cvta.to.shared.u64 t, %1; cvt.u32.u64 %0, t; }" : "=r"(a) : "l"(p));
    return a;
}

#define CP_ASYNC16(dst, src) \
    asm volatile("cp.async.cg.shared.global [%0], [%1], 16;" :: "r"(dst), "l"(src) : "memory")
#define CP_COMMIT()  asm volatile("cp.async.commit_group;" ::: "memory")
#define CP_WAIT0()   asm volatile("cp.async.wait_group 0;" ::: "memory")

// ldmatrix x4: per-lane addresses give A-frag {a0,a1,a2,a3} in mma order
#define LDSM_X4(r0, r1, r2, r3, addr)                                        \
    asm volatile("ldmatrix.sync.aligned.m8n8.x4.shared.b16 {%0,%1,%2,%3}, [%4];" \
        : "=r"(r0), "=r"(r1), "=r"(r2), "=r"(r3) : "r"(addr))

// m16n8k8 tf32 mma: D += A * B^T
__device__ __forceinline__ void mma1688(float* d, const uint32_t* a, const uint32_t* b) {
    asm volatile(
        "mma.sync.aligned.m16n8k8.row.col.f32.tf32.tf32.f32 "
        "{%0,%1,%2,%3}, {%4,%5,%6,%7}, {%8,%9}, {%0,%1,%2,%3};"
        : "+f"(d[0]), "+f"(d[1]), "+f"(d[2]), "+f"(d[3])
        : "r"(a[0]), "r"(a[1]), "r"(a[2]), "r"(a[3]), "r"(b[0]), "r"(b[1]));
}

#define APITCH 36   // row-major A staging pitch; conflict-free STS/LDSM

// ------------------------------- prep -------------------------------------
// Wt3/Wt2 in per-chunk B-fragment order (R8 mapping):
//   pos = ((nt*4+ks)*32 + lane)*2 + comp; o = nt*8+(lane>>2); k = ks*8+(lane&3)+comp*4
__global__ void prep_kernel(const float* __restrict__ w_exp3, const float* __restrict__ w_op3,
                            const float* __restrict__ w_exp2, const float* __restrict__ w_op2,
                            const float* __restrict__ w_red2, const float* __restrict__ b_exp3,
                            const float* __restrict__ b_op3, const float* __restrict__ b_exp2,
                            const float* __restrict__ b_op2, const float* __restrict__ b_red2,
                            const int* __restrict__ act) {
    int t = blockIdx.x * blockDim.x + threadIdx.x;
    int nth = gridDim.x * blockDim.x;
    if (t < 80) g_scal[t] = (float)act[t];
    if (t == 0) {
        int f0 = 0, f1 = 0, f2 = 0, f3 = 0;
        for (int b = 0; b < 8; b++) {
            f0 |= act[b * 10 + 0] | act[b * 10 + 1];
            f1 |= act[b * 10 + 2] | act[b * 10 + 3] | act[b * 10 + 4];
            f2 |= act[b * 10 + 5] | act[b * 10 + 6] | act[b * 10 + 7];
            f3 |= act[b * 10 + 8] | act[b * 10 + 9];
        }
        g_flags[0] = f0; g_flags[1] = f1; g_flags[2] = f2; g_flags[3] = f3;
    }
    for (int f = t; f < 24576; f += nth) {          // We3T[c*384 + m*64 + o]
        int o = f / 384, r = f % 384, m = r >> 6, c = r & 63;
        g_We3T[c * 384 + m * 64 + o] = w_exp3[f];
    }
    for (int f = t; f < 8 * 24576; f += nth) {
        int b = f / 24576, r = f % 24576;
        int ch = r >> 11, pos = r & 2047;
        int ntks = pos >> 6, lane = (pos >> 1) & 31, comp = pos & 1;
        int o = (ntks >> 2) * 8 + (lane >> 2);
        int k = (ntks & 3) * 8 + (lane & 3) + comp * 4;
        g_Wt3[f] = to_tf32((float)act[b * 10 + 9] * w_op3[o * 384 + ch * 32 + k]);
    }
    for (int f = t; f < 8 * 32768; f += nth) {
        int b = f >> 15, r = f & 32767;
        int ch = r >> 11, pos = r & 2047;
        int ntks = pos >> 6, lane = (pos >> 1) & 31, comp = pos & 1;
        int o = (ntks >> 2) * 8 + (lane >> 2);
        int k = (ntks & 3) * 8 + (lane & 3) + comp * 4;
        int cp = ch * 32 + k;
        float v;
        if (cp < 128)      v = (float)act[b * 10 + 5] * w_exp2[o * 128 + cp];
        else if (cp < 256) v = (float)act[b * 10 + 6] * w_op2[o * 128 + (cp - 128)];
        else               v = (float)act[b * 10 + 7] * w_red2[o * 256 + (cp - 256)];
        g_Wt2[f] = to_tf32(v);
    }
    for (int f = t; f < 512; f += nth) {
        int b = f >> 6, o = f & 63;
        g_bias3[f] = (float)act[b * 10 + 8] * b_exp3[o] + (float)act[b * 10 + 9] * b_op3[o];
        g_bias2[f] = (float)act[b * 10 + 5] * b_exp2[o] + (float)act[b * 10 + 6] * b_op2[o]
                   + (float)act[b * 10 + 7] * b_red2[o];
    }
}

// ----------------------------- reduce3 ----------------------------------
__global__ void __launch_bounds__(128) reduce3_kernel(const float* __restrict__ x3) {
    int sub = threadIdx.x >> 5;
    int c2 = threadIdx.x & 31;
    int blk = blockIdx.x * 4 + sub;             // b*1024 + i*32 + j
    int i = (blk >> 5) & 31, j = blk & 31;
    float ex0 = 0.0f, fa0 = 1.0f, ex1 = 0.0f, fa1 = 1.0f;
    float ex0b = 0.0f, fa0b = 1.0f, ex1b = 0.0f, fa1b = 1.0f;
    if (i != j) {
        const float2* base = (const float2*)(x3 + (size_t)blk * 2048) + c2;
#pragma unroll 4
        for (int k = 0; k < 32; k += 2) {
            float2 v0 = base[k * 32];
            float2 v1 = base[(k + 1) * 32];
            if (k != i && k != j) {
                ex0 = fmaxf(ex0, v0.x); fa0 = fminf(fa0, v0.x);
                ex0b = fmaxf(ex0b, v0.y); fa0b = fminf(fa0b, v0.y);
            }
            if (k + 1 != i && k + 1 != j) {
                ex1 = fmaxf(ex1, v1.x); fa1 = fminf(fa1, v1.x);
                ex1b = fmaxf(ex1b, v1.y); fa1b = fminf(fa1b, v1.y);
            }
        }
    }
    float4 r;
    r.x = fmaxf(ex0, ex1); r.y = fminf(fa0, fa1);
    r.z = fmaxf(ex0b, ex1b); r.w = fminf(fa0b, fa1b);
    if (i == j) { r.x = 0.0f; r.y = 1.0f; r.z = 0.0f; r.w = 1.0f; }
    *(float4*)(g_r3 + (size_t)blk * 128 + 4 * c2) = r;
}

// ------------- y2: block = (b*32+p, q-group of 8) ---------------------------
__global__ void __launch_bounds__(384) y2_kernel(const float* __restrict__ x2) {
    __shared__ float Ash[512];
    __shared__ float Wsh[16 * 384];
    int tid = threadIdx.x;
    int blk = blockIdx.x;               // (b*32+p)*4 + qg
    int bp = blk >> 2, qg = blk & 3;
    const float* xsrc = x2 + (size_t)bp * 2048 + qg * 512;
    for (int f = tid; f < 512; f += 384) Ash[f] = xsrc[f];
    float acc[8];
#pragma unroll
    for (int q = 0; q < 8; q++) acc[q] = 0.0f;
    for (int cc = 0; cc < 4; cc++) {
        __syncthreads();
#pragma unroll
        for (int it = 0; it < 16; it++)
            Wsh[it * 384 + tid] = g_We3T[cc * 6144 + it * 384 + tid];
        __syncthreads();
#pragma unroll
        for (int q = 0; q < 8; q++) {
            float s = acc[q];
#pragma unroll
            for (int c2 = 0; c2 < 16; c2++)
                s = fmaf(Ash[q * 64 + cc * 16 + c2], Wsh[c2 * 384 + tid], s);
            acc[q] = s;
        }
    }
#pragma unroll
    for (int q = 0; q < 8; q++)
        g_y2[((size_t)bp * 32 + qg * 8 + q) * 384 + tid] = acc[q];
}

// ----------------- pair sums P1/P2/P3 (a8 + bias folded) --------------------
__global__ void psum_kernel() {
    int t = blockIdx.x * blockDim.x + threadIdx.x;
    int o = t & 63, q = (t >> 6) & 31, p = (t >> 11) & 31, b = t >> 16;
    float a8 = g_scal[b * 10 + 8];
    size_t pq = ((size_t)(b * 32 + p) * 32 + q) * 384;
    size_t qp = ((size_t)(b * 32 + q) * 32 + p) * 384;
    g_P1[t] = a8 * (g_y2[pq + o] + g_y2[qp + 128 + o]) + g_bias3[b * 64 + o];
    g_P2[t] = a8 * (g_y2[pq + 64 + o] + g_y2[qp + 192 + o]);
    g_P3[t] = a8 * (g_y2[pq + 256 + o] + g_y2[qp + 320 + o]);
}

// -------------------- o0 + o1 merged (reductions fused) ----------------------
__global__ void o01_kernel(const float* __restrict__ x0, const float* __restrict__ x1,
                           const float* __restrict__ x2,
                           const float* __restrict__ w_op0, const float* __restrict__ b_op0,
                           const float* __restrict__ w_red0, const float* __restrict__ b_red0,
                           const float* __restrict__ w_exp1, const float* __restrict__ b_exp1,
                           const float* __restrict__ w_op1, const float* __restrict__ b_op1,
                           const float* __restrict__ w_red1, const float* __restrict__ b_red1,
                           float* __restrict__ out) {
    int o = threadIdx.x;
    if (blockIdx.x < 8) {
        int b = blockIdx.x;
        __shared__ float xs[64], rs[128];
        float ex = -INFINITY, fa = INFINITY;
        for (int i = 0; i < 32; i++) {
            float v = x1[(b * 32 + i) * 64 + o];
            ex = fmaxf(ex, v); fa = fminf(fa, v);
        }
        rs[2 * o] = ex; rs[2 * o + 1] = fa;
        xs[o] = x0[b * 64 + o];
        __syncthreads();
        float d0 = 0.0f, d1 = 0.0f;
#pragma unroll 8
        for (int c = 0; c < 64; c++) d0 = fmaf(w_op0[o * 64 + c], xs[c], d0);
#pragma unroll 8
        for (int c = 0; c < 128; c++) d1 = fmaf(w_red0[o * 128 + c], rs[c], d1);
        float s = g_scal[b * 10 + 0] * (d0 + b_op0[o]) + g_scal[b * 10 + 1] * (d1 + b_red0[o]);
        out[b * 64 + o] = g_flags[0] ? sigf(s) : 0.0f;
    } else {
        int blk = blockIdx.x - 8;       // b*32+i
        int b = blk >> 5, i = blk & 31;
        __shared__ float x0s[64], x1s[64], r2s[128];
        float ex = 0.0f, fa = 1.0f;
        const float* base = x2 + (size_t)blk * 2048;
        for (int j = 0; j < 32; j++) {
            if (j == i) continue;
            float v = base[j * 64 + o];
            ex = fmaxf(ex, v); fa = fminf(fa, v);
        }
        r2s[2 * o] = ex; r2s[2 * o + 1] = fa;
        x0s[o] = x0[b * 64 + o];
        x1s[o] = x1[blk * 64 + o];
        __syncthreads();
        float d0 = 0.0f, d1 = 0.0f, d2 = 0.0f;
#pragma unroll 8
        for (int c = 0; c < 64; c++) {
            d0 = fmaf(w_exp1[o * 64 + c], x0s[c], d0);
            d1 = fmaf(w_op1[o * 64 + c], x1s[c], d1);
        }
#pragma unroll 8
        for (int c = 0; c < 128; c++) d2 = fmaf(w_red1[o * 128 + c], r2s[c], d2);
        float s = g_scal[b * 10 + 2] * (d0 + b_exp1[o]) + g_scal[b * 10 + 3] * (d1 + b_op1[o])
                + g_scal[b * 10 + 4] * (d2 + b_red1[o]);
        out[O1_OFF + blk * 64 + o] = g_flags[1] ? sigf(s) : 0.0f;
    }
}

// ------ o3: mma.sync tf32, cp.async double-buffer, warp tile 32x64 -----------
__global__ void __launch_bounds__(128) o3t_kernel(const float* __restrict__ x3,
                                                  float* __restrict__ out) {
    extern __shared__ float sm[];
    float* Ws = sm + 2 * 128 * APITCH;  // [2][2048]
    uint32_t AsU = smem_u32(sm);
    uint32_t WsU = AsU + 2 * 128 * APITCH * 4;
    int tid = threadIdx.x, wid = tid >> 5, lane = tid & 31;
    int bid = blockIdx.x;
    int b = bid >> 8, r = bid & 255, i = r >> 3, j0 = (r & 7) << 2;
    const float* X = x3 + ((size_t)b << 21);
    const float* Wb = g_Wt3 + b * 24576;

    // ldmatrix lane offset: row = lane&15, col4 = (lane>>4)*4
    uint32_t aLaneOff = (uint32_t)(((lane & 15) * APITCH + ((lane >> 4) << 2)) * 4);
    uint32_t aTileBase = AsU + (uint32_t)(wid * 32 * APITCH * 4) + aLaneOff;

    float acc[2][8][4];
#pragma unroll
    for (int t2 = 0; t2 < 2; t2++)
#pragma unroll
        for (int nt = 0; nt < 8; nt++)
#pragma unroll
            for (int v = 0; v < 4; v++) acc[t2][nt][v] = 0.0f;

#define ISSUE_CH(ch, p) do {                                                    \
    int m_ = (ch) >> 1, c0_ = ((ch) & 1) << 5;                                  \
    int sj_, sk_, base_;                                                        \
    switch (m_) {                                                               \
        case 0: base_ = i * 1024; sj_ = 32;   sk_ = 1;    break;                \
        case 1: base_ = i * 1024; sj_ = 1;    sk_ = 32;   break;                \
        case 2: base_ = i * 32;   sj_ = 1024; sk_ = 1;    break;                \
        case 3: base_ = i * 32;   sj_ = 1;    sk_ = 1024; break;                \
        case 4: base_ = i;        sj_ = 1024; sk_ = 32;   break;                \
        default: base_ = i;       sj_ = 32;   sk_ = 1024; break;                \
    }                                                                           \
    uint32_t Adst_ = AsU + (p) * (128 * APITCH * 4);                            \
    _Pragma("unroll")                                                           \
    for (int it = 0; it < 8; it++) {                                            \
        int idx_ = tid + it * 128;                                              \
        int row_ = idx_ >> 3, seg_ = idx_ & 7;                                  \
        int j_ = j0 + (row_ >> 5), k_ = row_ & 31;                              \
        const float* src_ = X + (size_t)(base_ + j_ * sj_ + k_ * sk_) * 64      \
                            + c0_ + seg_ * 4;                                   \
        CP_ASYNC16(Adst_ + (uint32_t)(row_ * APITCH + seg_ * 4) * 4, src_);     \
    }                                                                           \
    uint32_t Wdst_ = WsU + (p) * 8192 + tid * 16;                               \
    const float* wsrc_ = Wb + (ch) * 2048 + tid * 4;                            \
    _Pragma("unroll")                                                           \
    for (int it = 0; it < 4; it++)                                              \
        CP_ASYNC16(Wdst_ + it * 2048, wsrc_ + it * 512);                        \
    CP_COMMIT();                                                                \
} while (0)

    ISSUE_CH(0, 0);

    for (int ch = 0; ch < 12; ch++) {
        int p = ch & 1;
        CP_WAIT0();
        __syncthreads();
        if (ch < 11) ISSUE_CH(ch + 1, 1 - p);
        uint32_t Abase = aTileBase + (uint32_t)(p * 128 * APITCH * 4);
        const float* Wp = Ws + p * 2048;
#pragma unroll
        for (int ks = 0; ks < 4; ks++) {
            uint32_t a0[4], a1[4];
            uint32_t addr0 = Abase + (uint32_t)(ks * 8 * 4);
            LDSM_X4(a0[0], a0[1], a0[2], a0[3], addr0);
            LDSM_X4(a1[0], a1[1], a1[2], a1[3], addr0 + 16 * APITCH * 4);
#pragma unroll
            for (int nt = 0; nt < 8; nt++) {
                uint2 bu = *(const uint2*)(Wp + ((nt * 4 + ks) * 32 + lane) * 2);
                uint32_t bf[2] = {bu.x, bu.y};
                mma1688(acc[0][nt], a0, bf);
                mma1688(acc[1][nt], a1, bf);
            }
        }
    }
#undef ISSUE_CH

    // epilogue: warp owns j = j0 + wid, all 32 k, all 64 cols
    int flag = g_flags[3];
    int g = lane >> 2, c2 = (lane & 3) * 2;
    int j = j0 + wid;
    const float* p1p = g_P1 + (((b * 32 + i) * 32 + j) << 6);
#pragma unroll
    for (int t2 = 0; t2 < 2; t2++) {
#pragma unroll
        for (int hi = 0; hi < 2; hi++) {
            int kk = t2 * 16 + g + 8 * hi;
            const float* p2p = g_P2 + (((b * 32 + i) * 32 + kk) << 6);
            const float* p3p = g_P3 + (((b * 32 + j) * 32 + kk) << 6);
            float* op = out + O3_OFF + ((((size_t)(b * 32 + i) * 32 + j) * 32 + kk) << 6);
#pragma unroll
            for (int nt = 0; nt < 8; nt++) {
                int col = nt * 8 + c2;
                float2 p1 = *(const float2*)(p1p + col);
                float2 p2 = *(const float2*)(p2p + col);
                float2 p3 = *(const float2*)(p3p + col);
                float v0 = acc[t2][nt][hi * 2] + p1.x + p2.x + p3.x;
                float v1 = acc[t2][nt][hi * 2 + 1] + p1.y + p2.y + p3.y;
                if (flag) { v0 = sigf(v0); v1 = sigf(v1); }
                else      { v0 = 0.0f; v1 = 0.0f; }
                float2 rr; rr.x = v0; rr.y = v1;
                *(float2*)(op + col) = rr;
            }
        }
    }
}

// ----------- o2 via mma.sync tf32, cp.async + ldmatrix, 256 thr --------------
__global__ void __launch_bounds__(256) o2t_kernel(const float* __restrict__ x1,
                                                  const float* __restrict__ x2,
                                                  float* __restrict__ out) {
    __shared__ float As[2][32 * APITCH];
    __shared__ float Ws[2][2048];
    uint32_t AsU = smem_u32(&As[0][0]);
    uint32_t WsU = smem_u32(&Ws[0][0]);
    int tid = threadIdx.x, wid = tid >> 5, lane = tid & 31;
    int mt = wid & 1, qt = wid >> 1;        // warp: tile mt x nt pair {2qt, 2qt+1}
    int bid = blockIdx.x;                   // b*32 + i
    int b = bid >> 5, i = bid & 31;
    const float* Wb = g_Wt2 + (size_t)b * 32768;

    int row = tid >> 3, seg = tid & 7;
    uint32_t sOfB = (uint32_t)(row * APITCH + seg * 4) * 4;
    int jv = row, segOf = seg * 4;
    uint32_t aLaneOff = (uint32_t)(((lane & 15) * APITCH + ((lane >> 4) << 2)) * 4);
    uint32_t aTileBase = AsU + (uint32_t)(mt * 16 * APITCH * 4) + aLaneOff;

    float acc[2][4];
#pragma unroll
    for (int n2 = 0; n2 < 2; n2++)
#pragma unroll
        for (int v = 0; v < 4; v++) acc[n2][v] = 0.0f;

#define ISSUE_CH2(ch, p) do {                                                    \
    int cp_ = (ch) * 32 + segOf;                                                 \
    const float* src_;                                                           \
    if (cp_ < 64)       src_ = x1 + (b * 32 + i) * 64 + cp_;                     \
    else if (cp_ < 128) src_ = x1 + (b * 32 + jv) * 64 + (cp_ - 64);             \
    else if (cp_ < 192) src_ = x2 + ((size_t)(b * 32 + i) * 32 + jv) * 64 + (cp_ - 128); \
    else if (cp_ < 256) src_ = x2 + ((size_t)(b * 32 + jv) * 32 + i) * 64 + (cp_ - 192); \
    else if (cp_ < 384) src_ = g_r3 + ((size_t)(b * 32 + i) * 32 + jv) * 128 + (cp_ - 256); \
    else                src_ = g_r3 + ((size_t)(b * 32 + jv) * 32 + i) * 128 + (cp_ - 384); \
    CP_ASYNC16(AsU + (p) * (32 * APITCH * 4) + sOfB, src_);                      \
    uint32_t Wdst_ = WsU + (p) * 8192 + tid * 16;                                \
    const float* wsrc_ = Wb + (ch) * 2048 + tid * 4;                             \
    CP_ASYNC16(Wdst_, wsrc_);                                                    \
    CP_ASYNC16(Wdst_ + 4096, wsrc_ + 1024);                                      \
    CP_COMMIT();                                                                 \
} while (0)

    ISSUE_CH2(0, 0);

    for (int ch = 0; ch < 16; ch++) {
        int p = ch & 1;
        CP_WAIT0();
        __syncthreads();
        if (ch < 15) ISSUE_CH2(ch + 1, 1 - p);
        uint32_t Abase = aTileBase + (uint32_t)(p * 32 * APITCH * 4);
        const float* Wp = &Ws[p][0];
#pragma unroll
        for (int ks = 0; ks < 4; ks++) {
            uint32_t a[4];
            LDSM_X4(a[0], a[1], a[2], a[3], Abase + (uint32_t)(ks * 8 * 4));
#pragma unroll
            for (int n2 = 0; n2 < 2; n2++) {
                int nt = qt * 2 + n2;
                uint2 bu = *(const uint2*)(Wp + ((nt * 4 + ks) * 32 + lane) * 2);
                uint32_t bf[2] = {bu.x, bu.y};
                mma1688(acc[n2], a, bf);
            }
        }
    }
#undef ISSUE_CH2

    int flag = g_flags[2];
    int g = lane >> 2, c2 = (lane & 3) * 2;
#pragma unroll
    for (int hi = 0; hi < 2; hi++) {
        int j = mt * 16 + g + 8 * hi;
        const float* bsp = g_bias2 + b * 64;
        float* op = out + O2_OFF + (((size_t)(b * 32 + i) * 32 + j) << 6);
#pragma unroll
        for (int n2 = 0; n2 < 2; n2++) {
            int col = (qt * 2 + n2) * 8 + c2;
            float2 bs = *(const float2*)(bsp + col);
            float v0 = acc[n2][hi * 2] + bs.x;
            float v1 = acc[n2][hi * 2 + 1] + bs.y;
            if (flag) { v0 = sigf(v0); v1 = sigf(v1); }
            else      { v0 = 0.0f; v1 = 0.0f; }
            float2 rr; rr.x = v0; rr.y = v1;
            *(float2*)(op + col) = rr;
        }
    }
}

// ------------------------------- launch -------------------------------------
extern "C" void kernel_launch(void* const* d_in, const int* in_sizes, int n_in,
                              void* d_out, int out_size) {
    const float* x0 = (const float*)d_in[0];
    const float* x1 = (const float*)d_in[1];
    const float* x2 = (const float*)d_in[2];
    const float* x3 = (const float*)d_in[3];
    const float* w_op0 = (const float*)d_in[4];
    const float* b_op0 = (const float*)d_in[5];
    const float* w_red0 = (const float*)d_in[6];
    const float* b_red0 = (const float*)d_in[7];
    const float* w_exp1 = (const float*)d_in[8];
    const float* b_exp1 = (const float*)d_in[9];
    const float* w_op1 = (const float*)d_in[10];
    const float* b_op1 = (const float*)d_in[11];
    const float* w_red1 = (const float*)d_in[12];
    const float* b_red1 = (const float*)d_in[13];
    const float* w_exp2 = (const float*)d_in[14];
    const float* b_exp2 = (const float*)d_in[15];
    const float* w_op2 = (const float*)d_in[16];
    const float* b_op2 = (const float*)d_in[17];
    const float* w_red2 = (const float*)d_in[18];
    const float* b_red2 = (const float*)d_in[19];
    const float* w_exp3 = (const float*)d_in[20];
    const float* b_exp3 = (const float*)d_in[21];
    const float* w_op3 = (const float*)d_in[22];
    const float* b_op3 = (const float*)d_in[23];
    const int* act = (const int*)d_in[24];
    float* out = (float*)d_out;

    const int O3T_SMEM = (2 * 128 * APITCH + 2 * 2048) * 4;   // 53248 B
    cudaFuncSetAttribute(o3t_kernel, cudaFuncAttributeMaxDynamicSharedMemorySize, O3T_SMEM);

    prep_kernel<<<64, 256>>>(w_exp3, w_op3, w_exp2, w_op2, w_red2,
                             b_exp3, b_op3, b_exp2, b_op2, b_red2, act);
    y2_kernel<<<1024, 384>>>(x2);
    psum_kernel<<<2048, 256>>>();
    o3t_kernel<<<2048, 128, O3T_SMEM>>>(x3, out);
    reduce3_kernel<<<2048, 128>>>(x3);
    o2t_kernel<<<256, 256>>>(x1, x2, out);
    o01_kernel<<<264, 64>>>(x0, x1, x2, w_op0, b_op0, w_red0, b_red0,
                            w_exp1, b_exp1, w_op1, b_op1, w_red1, b_red1, out);
}

// round 14
// speedup vs baseline: 1.0470x; 1.0470x over previous
#include <cuda_runtime.h>
#include <math.h>
#include <stdint.h>

// B=8, n=32, C=64, O=64
// out: concat(o0[8,64], o1[8,32,64], o2[8,32,32,64], o3[8,32,32,32,64]) f32

#define O1_OFF 512
#define O2_OFF 16896
#define O3_OFF 541184

// ---------------- device scratch ----------------
__device__ __align__(16) float g_We3T[384 * 64];
__device__ __align__(16) float g_Wt3[8 * 12 * 2048];   // [b][chunk][frag-order], tf32
__device__ __align__(16) float g_Wt2[8 * 16 * 2048];   // [b][chunk][frag-order], tf32
__device__ __align__(16) float g_bias3[8 * 64];
__device__ __align__(16) float g_bias2[8 * 64];
__device__ __align__(16) float g_scal[8 * 10];
__device__ int g_flags[4];
__device__ __align__(16) float g_r3[8 * 32 * 32 * 128];
__device__ __align__(16) float g_y2[8 * 32 * 32 * 384];
__device__ __align__(16) float g_P1[8 * 32 * 32 * 64];
__device__ __align__(16) float g_P2[8 * 32 * 32 * 64];
__device__ __align__(16) float g_P3[8 * 32 * 32 * 64];

__device__ __forceinline__ float sigf(float x) { return 1.0f / (1.0f + __expf(-x)); }

__device__ __forceinline__ float to_tf32(float x) {
    uint32_t u;
    asm("cvt.rna.tf32.f32 %0, %1;" : "=r"(u) : "f"(x));
    return __uint_as_float(u);
}

__device__ __forceinline__ uint32_t smem_u32(const void* p) {
    uint32_t a;
    asm("{ .reg .u64 t; cvta.to.shared.u64 t, %1; cvt.u32.u64 %0, t; }" : "=r"(a) : "l"(p));
    return a;
}

#define CP_ASYNC16(dst, src) \
    asm volatile("cp.async.cg.shared.global [%0], [%1], 16;" :: "r"(dst), "l"(src) : "memory")
#define CP_COMMIT()  asm volatile("cp.async.commit_group;" ::: "memory")
#define CP_WAIT0()   asm volatile("cp.async.wait_group 0;" ::: "memory")

// ldmatrix x4: per-lane addresses give A-frag {a0,a1,a2,a3} in mma order
#define LDSM_X4(r0, r1, r2, r3, addr)                                        \
    asm volatile("ldmatrix.sync.aligned.m8n8.x4.shared.b16 {%0,%1,%2,%3}, [%4];" \
        : "=r"(r0), "=r"(r1), "=r"(r2), "=r"(r3) : "r"(addr))

// m16n8k8 tf32 mma: D += A * B^T
__device__ __forceinline__ void mma1688(float* d, const uint32_t* a, const uint32_t* b) {
    asm volatile(
        "mma.sync.aligned.m16n8k8.row.col.f32.tf32.tf32.f32 "
        "{%0,%1,%2,%3}, {%4,%5,%6,%7}, {%8,%9}, {%0,%1,%2,%3};"
        : "+f"(d[0]), "+f"(d[1]), "+f"(d[2]), "+f"(d[3])
        : "r"(a[0]), "r"(a[1]), "r"(a[2]), "r"(a[3]), "r"(b[0]), "r"(b[1]));
}

#define APITCH 36   // row-major A staging pitch; conflict-free STS/LDSM

// ------------------------------- prep -------------------------------------
// Wt3/Wt2 in per-chunk B-fragment order (R8 mapping):
//   pos = ((nt*4+ks)*32 + lane)*2 + comp; o = nt*8+(lane>>2); k = ks*8+(lane&3)+comp*4
__global__ void prep_kernel(const float* __restrict__ w_exp3, const float* __restrict__ w_op3,
                            const float* __restrict__ w_exp2, const float* __restrict__ w_op2,
                            const float* __restrict__ w_red2, const float* __restrict__ b_exp3,
                            const float* __restrict__ b_op3, const float* __restrict__ b_exp2,
                            const float* __restrict__ b_op2, const float* __restrict__ b_red2,
                            const int* __restrict__ act) {
    int t = blockIdx.x * blockDim.x + threadIdx.x;
    int nth = gridDim.x * blockDim.x;
    if (t < 80) g_scal[t] = (float)act[t];
    if (t == 0) {
        int f0 = 0, f1 = 0, f2 = 0, f3 = 0;
        for (int b = 0; b < 8; b++) {
            f0 |= act[b * 10 + 0] | act[b * 10 + 1];
            f1 |= act[b * 10 + 2] | act[b * 10 + 3] | act[b * 10 + 4];
            f2 |= act[b * 10 + 5] | act[b * 10 + 6] | act[b * 10 + 7];
            f3 |= act[b * 10 + 8] | act[b * 10 + 9];
        }
        g_flags[0] = f0; g_flags[1] = f1; g_flags[2] = f2; g_flags[3] = f3;
    }
    for (int f = t; f < 24576; f += nth) {          // We3T[c*384 + m*64 + o]
        int o = f / 384, r = f % 384, m = r >> 6, c = r & 63;
        g_We3T[c * 384 + m * 64 + o] = w_exp3[f];
    }
    for (int f = t; f < 8 * 24576; f += nth) {
        int b = f / 24576, r = f % 24576;
        int ch = r >> 11, pos = r & 2047;
        int ntks = pos >> 6, lane = (pos >> 1) & 31, comp = pos & 1;
        int o = (ntks >> 2) * 8 + (lane >> 2);
        int k = (ntks & 3) * 8 + (lane & 3) + comp * 4;
        g_Wt3[f] = to_tf32((float)act[b * 10 + 9] * w_op3[o * 384 + ch * 32 + k]);
    }
    for (int f = t; f < 8 * 32768; f += nth) {
        int b = f >> 15, r = f & 32767;
        int ch = r >> 11, pos = r & 2047;
        int ntks = pos >> 6, lane = (pos >> 1) & 31, comp = pos & 1;
        int o = (ntks >> 2) * 8 + (lane >> 2);
        int k = (ntks & 3) * 8 + (lane & 3) + comp * 4;
        int cp = ch * 32 + k;
        float v;
        if (cp < 128)      v = (float)act[b * 10 + 5] * w_exp2[o * 128 + cp];
        else if (cp < 256) v = (float)act[b * 10 + 6] * w_op2[o * 128 + (cp - 128)];
        else               v = (float)act[b * 10 + 7] * w_red2[o * 256 + (cp - 256)];
        g_Wt2[f] = to_tf32(v);
    }
    for (int f = t; f < 512; f += nth) {
        int b = f >> 6, o = f & 63;
        g_bias3[f] = (float)act[b * 10 + 8] * b_exp3[o] + (float)act[b * 10 + 9] * b_op3[o];
        g_bias2[f] = (float)act[b * 10 + 5] * b_exp2[o] + (float)act[b * 10 + 6] * b_op2[o]
                   + (float)act[b * 10 + 7] * b_red2[o];
    }
}

// ------------- y2: block = (b*32+p, q-group of 8) ---------------------------
__global__ void __launch_bounds__(384) y2_kernel(const float* __restrict__ x2) {
    __shared__ float Ash[512];
    __shared__ float Wsh[16 * 384];
    int tid = threadIdx.x;
    int blk = blockIdx.x;               // (b*32+p)*4 + qg
    int bp = blk >> 2, qg = blk & 3;
    const float* xsrc = x2 + (size_t)bp * 2048 + qg * 512;
    for (int f = tid; f < 512; f += 384) Ash[f] = xsrc[f];
    float acc[8];
#pragma unroll
    for (int q = 0; q < 8; q++) acc[q] = 0.0f;
    for (int cc = 0; cc < 4; cc++) {
        __syncthreads();
#pragma unroll
        for (int it = 0; it < 16; it++)
            Wsh[it * 384 + tid] = g_We3T[cc * 6144 + it * 384 + tid];
        __syncthreads();
#pragma unroll
        for (int q = 0; q < 8; q++) {
            float s = acc[q];
#pragma unroll
            for (int c2 = 0; c2 < 16; c2++)
                s = fmaf(Ash[q * 64 + cc * 16 + c2], Wsh[c2 * 384 + tid], s);
            acc[q] = s;
        }
    }
#pragma unroll
    for (int q = 0; q < 8; q++)
        g_y2[((size_t)bp * 32 + qg * 8 + q) * 384 + tid] = acc[q];
}

// ----------------- pair sums P1/P2/P3 (a8 + bias folded) --------------------
__global__ void psum_kernel() {
    int t = blockIdx.x * blockDim.x + threadIdx.x;
    int o = t & 63, q = (t >> 6) & 31, p = (t >> 11) & 31, b = t >> 16;
    float a8 = g_scal[b * 10 + 8];
    size_t pq = ((size_t)(b * 32 + p) * 32 + q) * 384;
    size_t qp = ((size_t)(b * 32 + q) * 32 + p) * 384;
    g_P1[t] = a8 * (g_y2[pq + o] + g_y2[qp + 128 + o]) + g_bias3[b * 64 + o];
    g_P2[t] = a8 * (g_y2[pq + 64 + o] + g_y2[qp + 192 + o]);
    g_P3[t] = a8 * (g_y2[pq + 256 + o] + g_y2[qp + 320 + o]);
}

// -------------------- o0 + o1 merged (reductions fused) ----------------------
__global__ void o01_kernel(const float* __restrict__ x0, const float* __restrict__ x1,
                           const float* __restrict__ x2,
                           const float* __restrict__ w_op0, const float* __restrict__ b_op0,
                           const float* __restrict__ w_red0, const float* __restrict__ b_red0,
                           const float* __restrict__ w_exp1, const float* __restrict__ b_exp1,
                           const float* __restrict__ w_op1, const float* __restrict__ b_op1,
                           const float* __restrict__ w_red1, const float* __restrict__ b_red1,
                           float* __restrict__ out) {
    int o = threadIdx.x;
    if (blockIdx.x < 8) {
        int b = blockIdx.x;
        __shared__ float xs[64], rs[128];
        float ex = -INFINITY, fa = INFINITY;
        for (int i = 0; i < 32; i++) {
            float v = x1[(b * 32 + i) * 64 + o];
            ex = fmaxf(ex, v); fa = fminf(fa, v);
        }
        rs[2 * o] = ex; rs[2 * o + 1] = fa;
        xs[o] = x0[b * 64 + o];
        __syncthreads();
        float d0 = 0.0f, d1 = 0.0f;
#pragma unroll 8
        for (int c = 0; c < 64; c++) d0 = fmaf(w_op0[o * 64 + c], xs[c], d0);
#pragma unroll 8
        for (int c = 0; c < 128; c++) d1 = fmaf(w_red0[o * 128 + c], rs[c], d1);
        float s = g_scal[b * 10 + 0] * (d0 + b_op0[o]) + g_scal[b * 10 + 1] * (d1 + b_red0[o]);
        out[b * 64 + o] = g_flags[0] ? sigf(s) : 0.0f;
    } else {
        int blk = blockIdx.x - 8;       // b*32+i
        int b = blk >> 5, i = blk & 31;
        __shared__ float x0s[64], x1s[64], r2s[128];
        float ex = 0.0f, fa = 1.0f;
        const float* base = x2 + (size_t)blk * 2048;
        for (int j = 0; j < 32; j++) {
            if (j == i) continue;
            float v = base[j * 64 + o];
            ex = fmaxf(ex, v); fa = fminf(fa, v);
        }
        r2s[2 * o] = ex; r2s[2 * o + 1] = fa;
        x0s[o] = x0[b * 64 + o];
        x1s[o] = x1[blk * 64 + o];
        __syncthreads();
        float d0 = 0.0f, d1 = 0.0f, d2 = 0.0f;
#pragma unroll 8
        for (int c = 0; c < 64; c++) {
            d0 = fmaf(w_exp1[o * 64 + c], x0s[c], d0);
            d1 = fmaf(w_op1[o * 64 + c], x1s[c], d1);
        }
#pragma unroll 8
        for (int c = 0; c < 128; c++) d2 = fmaf(w_red1[o * 128 + c], r2s[c], d2);
        float s = g_scal[b * 10 + 2] * (d0 + b_exp1[o]) + g_scal[b * 10 + 3] * (d1 + b_op1[o])
                + g_scal[b * 10 + 4] * (d2 + b_red1[o]);
        out[O1_OFF + blk * 64 + o] = g_flags[1] ? sigf(s) : 0.0f;
    }
}

// ---- fused: o3 (blocks 0..2047, R12 config) + reduce3 (blocks 2048..3071) ---
__global__ void __launch_bounds__(256, 4) o3t_kernel(const float* __restrict__ x3,
                                                     float* __restrict__ out) {
    extern __shared__ float sm[];
    int tid = threadIdx.x, wid = tid >> 5, lane = tid & 31;
    int bid = blockIdx.x;

    if (bid >= 2048) {
        // ---------------- reduce3 branch: 8 (i,j)-cells per block ------------
        int cell = (bid - 2048) * 8 + (tid >> 5);    // b*1024 + i*32 + j
        int c2 = lane;
        int i = (cell >> 5) & 31, j = cell & 31;
        float ex0 = 0.0f, fa0 = 1.0f, ex1 = 0.0f, fa1 = 1.0f;
        float ex0b = 0.0f, fa0b = 1.0f, ex1b = 0.0f, fa1b = 1.0f;
        if (i != j) {
            const float2* base = (const float2*)(x3 + (size_t)cell * 2048) + c2;
#pragma unroll 4
            for (int k = 0; k < 32; k += 2) {
                float2 v0 = base[k * 32];
                float2 v1 = base[(k + 1) * 32];
                if (k != i && k != j) {
                    ex0 = fmaxf(ex0, v0.x); fa0 = fminf(fa0, v0.x);
                    ex0b = fmaxf(ex0b, v0.y); fa0b = fminf(fa0b, v0.y);
                }
                if (k + 1 != i && k + 1 != j) {
                    ex1 = fmaxf(ex1, v1.x); fa1 = fminf(fa1, v1.x);
                    ex1b = fmaxf(ex1b, v1.y); fa1b = fminf(fa1b, v1.y);
                }
            }
        }
        float4 rr;
        rr.x = fmaxf(ex0, ex1); rr.y = fminf(fa0, fa1);
        rr.z = fmaxf(ex0b, ex1b); rr.w = fminf(fa0b, fa1b);
        if (i == j) { rr.x = 0.0f; rr.y = 1.0f; rr.z = 0.0f; rr.w = 1.0f; }
        *(float4*)(g_r3 + (size_t)cell * 128 + 4 * c2) = rr;
        return;
    }

    // ---------------- o3 branch (R12 config) ----------------
    float* Ws = sm + 2 * 128 * APITCH;  // [2][2048]
    uint32_t AsU = smem_u32(sm);
    uint32_t WsU = AsU + 2 * 128 * APITCH * 4;
    int mtp = wid & 3, half = wid >> 2;
    int b = bid >> 8, r = bid & 255, i = r >> 3, j0 = (r & 7) << 2;
    const float* X = x3 + ((size_t)b << 21);
    const float* Wb = g_Wt3 + b * 24576;

    uint32_t sOfB[4];
    int jv[4], kv[4], segOf[4];
#pragma unroll
    for (int it = 0; it < 4; it++) {
        int idx = tid + it * 256;
        int row = idx >> 3, seg = idx & 7;
        sOfB[it] = (uint32_t)(row * APITCH + seg * 4) * 4;
        jv[it] = j0 + (row >> 5);
        kv[it] = row & 31;
        segOf[it] = seg * 4;
    }
    uint32_t aLaneOff = (uint32_t)(((lane & 15) * APITCH + ((lane >> 4) << 2)) * 4);
    uint32_t aTileBase = AsU + (uint32_t)(mtp * 32 * APITCH * 4) + aLaneOff;

    float acc[2][4][4];
#pragma unroll
    for (int t2 = 0; t2 < 2; t2++)
#pragma unroll
        for (int n4 = 0; n4 < 4; n4++)
#pragma unroll
            for (int v = 0; v < 4; v++) acc[t2][n4][v] = 0.0f;

#define ISSUE_CH(ch, p) do {                                                    \
    int m_ = (ch) >> 1, c0_ = ((ch) & 1) << 5;                                  \
    int sj_, sk_, base_;                                                        \
    switch (m_) {                                                               \
        case 0: base_ = i * 1024; sj_ = 32;   sk_ = 1;    break;                \
        case 1: base_ = i * 1024; sj_ = 1;    sk_ = 32;   break;                \
        case 2: base_ = i * 32;   sj_ = 1024; sk_ = 1;    break;                \
        case 3: base_ = i * 32;   sj_ = 1;    sk_ = 1024; break;                \
        case 4: base_ = i;        sj_ = 1024; sk_ = 32;   break;                \
        default: base_ = i;       sj_ = 32;   sk_ = 1024; break;                \
    }                                                                           \
    uint32_t Adst_ = AsU + (p) * (128 * APITCH * 4);                            \
    _Pragma("unroll")                                                           \
    for (int it = 0; it < 4; it++) {                                            \
        const float* src_ = X + (size_t)(base_ + jv[it] * sj_ + kv[it] * sk_) * 64 \
                            + c0_ + segOf[it];                                  \
        CP_ASYNC16(Adst_ + sOfB[it], src_);                                     \
    }                                                                           \
    uint32_t Wdst_ = WsU + (p) * 8192 + tid * 16;                               \
    const float* wsrc_ = Wb + (ch) * 2048 + tid * 4;                            \
    CP_ASYNC16(Wdst_, wsrc_);                                                   \
    CP_ASYNC16(Wdst_ + 4096, wsrc_ + 1024);                                     \
    CP_COMMIT();                                                                \
} while (0)

    ISSUE_CH(0, 0);

    for (int ch = 0; ch < 12; ch++) {
        int p = ch & 1;
        CP_WAIT0();
        __syncthreads();
        if (ch < 11) ISSUE_CH(ch + 1, 1 - p);
        uint32_t Abase = aTileBase + (uint32_t)(p * 128 * APITCH * 4);
        const float* Wp = Ws + p * 2048;
#pragma unroll
        for (int ks = 0; ks < 4; ks++) {
            uint32_t a0[4], a1[4];
            uint32_t addr0 = Abase + (uint32_t)(ks * 8 * 4);
            LDSM_X4(a0[0], a0[1], a0[2], a0[3], addr0);
            LDSM_X4(a1[0], a1[1], a1[2], a1[3], addr0 + 16 * APITCH * 4);
#pragma unroll
            for (int n4 = 0; n4 < 4; n4++) {
                int nt = half * 4 + n4;
                uint2 bu = *(const uint2*)(Wp + ((nt * 4 + ks) * 32 + lane) * 2);
                uint32_t bf[2] = {bu.x, bu.y};
                mma1688(acc[0][n4], a0, bf);
                mma1688(acc[1][n4], a1, bf);
            }
        }
    }
#undef ISSUE_CH

    // epilogue
    int flag = g_flags[3];
    int g = lane >> 2, c2 = (lane & 3) * 2;
#pragma unroll
    for (int t2 = 0; t2 < 2; t2++) {
        int tile = 2 * mtp + t2;
#pragma unroll
        for (int hi = 0; hi < 2; hi++) {
            int row = tile * 16 + g + 8 * hi;
            int jj = row >> 5, kk = row & 31, j = j0 + jj;
            const float* p1p = g_P1 + (((b * 32 + i) * 32 + j) << 6);
            const float* p2p = g_P2 + (((b * 32 + i) * 32 + kk) << 6);
            const float* p3p = g_P3 + (((b * 32 + j) * 32 + kk) << 6);
            float* op = out + O3_OFF + ((((size_t)(b * 32 + i) * 32 + j) * 32 + kk) << 6);
#pragma unroll
            for (int n4 = 0; n4 < 4; n4++) {
                int col = (half * 4 + n4) * 8 + c2;
                float2 p1 = *(const float2*)(p1p + col);
                float2 p2 = *(const float2*)(p2p + col);
                float2 p3 = *(const float2*)(p3p + col);
                float v0 = acc[t2][n4][hi * 2] + p1.x + p2.x + p3.x;
                float v1 = acc[t2][n4][hi * 2 + 1] + p1.y + p2.y + p3.y;
                if (flag) { v0 = sigf(v0); v1 = sigf(v1); }
                else      { v0 = 0.0f; v1 = 0.0f; }
                float2 rr; rr.x = v0; rr.y = v1;
                *(float2*)(op + col) = rr;
            }
        }
    }
}

// ----------- o2 via mma.sync tf32, cp.async + ldmatrix, 256 thr --------------
__global__ void __launch_bounds__(256) o2t_kernel(const float* __restrict__ x1,
                                                  const float* __restrict__ x2,
                                                  float* __restrict__ out) {
    __shared__ float As[2][32 * APITCH];
    __shared__ float Ws[2][2048];
    uint32_t AsU = smem_u32(&As[0][0]);
    uint32_t WsU = smem_u32(&Ws[0][0]);
    int tid = threadIdx.x, wid = tid >> 5, lane = tid & 31;
    int mt = wid & 1, qt = wid >> 1;        // warp: tile mt x nt pair {2qt, 2qt+1}
    int bid = blockIdx.x;                   // b*32 + i
    int b = bid >> 5, i = bid & 31;
    const float* Wb = g_Wt2 + (size_t)b * 32768;

    int row = tid >> 3, seg = tid & 7;
    uint32_t sOfB = (uint32_t)(row * APITCH + seg * 4) * 4;
    int jv = row, segOf = seg * 4;
    uint32_t aLaneOff = (uint32_t)(((lane & 15) * APITCH + ((lane >> 4) << 2)) * 4);
    uint32_t aTileBase = AsU + (uint32_t)(mt * 16 * APITCH * 4) + aLaneOff;

    float acc[2][4];
#pragma unroll
    for (int n2 = 0; n2 < 2; n2++)
#pragma unroll
        for (int v = 0; v < 4; v++) acc[n2][v] = 0.0f;

#define ISSUE_CH2(ch, p) do {                                                    \
    int cp_ = (ch) * 32 + segOf;                                                 \
    const float* src_;                                                           \
    if (cp_ < 64)       src_ = x1 + (b * 32 + i) * 64 + cp_;                     \
    else if (cp_ < 128) src_ = x1 + (b * 32 + jv) * 64 + (cp_ - 64);             \
    else if (cp_ < 192) src_ = x2 + ((size_t)(b * 32 + i) * 32 + jv) * 64 + (cp_ - 128); \
    else if (cp_ < 256) src_ = x2 + ((size_t)(b * 32 + jv) * 32 + i) * 64 + (cp_ - 192); \
    else if (cp_ < 384) src_ = g_r3 + ((size_t)(b * 32 + i) * 32 + jv) * 128 + (cp_ - 256); \
    else                src_ = g_r3 + ((size_t)(b * 32 + jv) * 32 + i) * 128 + (cp_ - 384); \
    CP_ASYNC16(AsU + (p) * (32 * APITCH * 4) + sOfB, src_);                      \
    uint32_t Wdst_ = WsU + (p) * 8192 + tid * 16;                                \
    const float* wsrc_ = Wb + (ch) * 2048 + tid * 4;                             \
    CP_ASYNC16(Wdst_, wsrc_);                                                    \
    CP_ASYNC16(Wdst_ + 4096, wsrc_ + 1024);                                      \
    CP_COMMIT();                                                                 \
} while (0)

    ISSUE_CH2(0, 0);

    for (int ch = 0; ch < 16; ch++) {
        int p = ch & 1;
        CP_WAIT0();
        __syncthreads();
        if (ch < 15) ISSUE_CH2(ch + 1, 1 - p);
        uint32_t Abase = aTileBase + (uint32_t)(p * 32 * APITCH * 4);
        const float* Wp = &Ws[p][0];
#pragma unroll
        for (int ks = 0; ks < 4; ks++) {
            uint32_t a[4];
            LDSM_X4(a[0], a[1], a[2], a[3], Abase + (uint32_t)(ks * 8 * 4));
#pragma unroll
            for (int n2 = 0; n2 < 2; n2++) {
                int nt = qt * 2 + n2;
                uint2 bu = *(const uint2*)(Wp + ((nt * 4 + ks) * 32 + lane) * 2);
                uint32_t bf[2] = {bu.x, bu.y};
                mma1688(acc[n2], a, bf);
            }
        }
    }
#undef ISSUE_CH2

    int flag = g_flags[2];
    int g = lane >> 2, c2 = (lane & 3) * 2;
#pragma unroll
    for (int hi = 0; hi < 2; hi++) {
        int j = mt * 16 + g + 8 * hi;
        const float* bsp = g_bias2 + b * 64;
        float* op = out + O2_OFF + (((size_t)(b * 32 + i) * 32 + j) << 6);
#pragma unroll
        for (int n2 = 0; n2 < 2; n2++) {
            int col = (qt * 2 + n2) * 8 + c2;
            float2 bs = *(const float2*)(bsp + col);
            float v0 = acc[n2][hi * 2] + bs.x;
            float v1 = acc[n2][hi * 2 + 1] + bs.y;
            if (flag) { v0 = sigf(v0); v1 = sigf(v1); }
            else      { v0 = 0.0f; v1 = 0.0f; }
            float2 rr; rr.x = v0; rr.y = v1;
            *(float2*)(op + col) = rr;
        }
    }
}

// ------------------------------- launch -------------------------------------
extern "C" void kernel_launch(void* const* d_in, const int* in_sizes, int n_in,
                              void* d_out, int out_size) {
    const float* x0 = (const float*)d_in[0];
    const float* x1 = (const float*)d_in[1];
    const float* x2 = (const float*)d_in[2];
    const float* x3 = (const float*)d_in[3];
    const float* w_op0 = (const float*)d_in[4];
    const float* b_op0 = (const float*)d_in[5];
    const float* w_red0 = (const float*)d_in[6];
    const float* b_red0 = (const float*)d_in[7];
    const float* w_exp1 = (const float*)d_in[8];
    const float* b_exp1 = (const float*)d_in[9];
    const float* w_op1 = (const float*)d_in[10];
    const float* b_op1 = (const float*)d_in[11];
    const float* w_red1 = (const float*)d_in[12];
    const float* b_red1 = (const float*)d_in[13];
    const float* w_exp2 = (const float*)d_in[14];
    const float* b_exp2 = (const float*)d_in[15];
    const float* w_op2 = (const float*)d_in[16];
    const float* b_op2 = (const float*)d_in[17];
    const float* w_red2 = (const float*)d_in[18];
    const float* b_red2 = (const float*)d_in[19];
    const float* w_exp3 = (const float*)d_in[20];
    const float* b_exp3 = (const float*)d_in[21];
    const float* w_op3 = (const float*)d_in[22];
    const float* b_op3 = (const float*)d_in[23];
    const int* act = (const int*)d_in[24];
    float* out = (float*)d_out;

    const int O3T_SMEM = (2 * 128 * APITCH + 2 * 2048) * 4;   // 53248 B
    cudaFuncSetAttribute(o3t_kernel, cudaFuncAttributeMaxDynamicSharedMemorySize, O3T_SMEM);

    prep_kernel<<<64, 256>>>(w_exp3, w_op3, w_exp2, w_op2, w_red2,
                             b_exp3, b_op3, b_exp2, b_op2, b_red2, act);
    y2_kernel<<<1024, 384>>>(x2);
    psum_kernel<<<2048, 256>>>();
    o3t_kernel<<<3072, 256, O3T_SMEM>>>(x3, out);   // o3 (0..2047) + reduce3 (2048..3071)
    o2t_kernel<<<256, 256>>>(x1, x2, out);
    o01_kernel<<<264, 64>>>(x0, x1, x2, w_op0, b_op0, w_red0, b_red0,
                            w_exp1, b_exp1, w_op1, b_op1, w_red1, b_red1, out);
}